// round 2
// baseline (speedup 1.0000x reference)
#include <cuda_runtime.h>

// ---------------- scratch (static, no allocations) ----------------
#define MAXN 1000000
#define MAXG 1000

__device__ float g_h[MAXN * 6];     // hidden state between layers
__device__ float g_agg[MAXN * 6];   // per-layer aggregation buffer
__device__ float g_pool[MAXG * 6];  // graph pooling sums
__device__ float g_cnt[MAXG];       // graph node counts

// vectorized fp32 reduction (sm_90+): 2 floats, 8B-aligned target
__device__ __forceinline__ void red2(float* p, float a, float b) {
    asm volatile("red.global.add.v2.f32 [%0], {%1, %2};"
                 :: "l"(p), "f"(a), "f"(b) : "memory");
}

// ---------------- kernels ----------------

__global__ void zero_kernel(int n6) {
    int i = blockIdx.x * blockDim.x + threadIdx.x;
    if (i < n6) g_agg[i] = 0.f;
    if (i < MAXG * 6) g_pool[i] = 0.f;
    if (i < MAXG) g_cnt[i] = 0.f;
}

// message + aggregate: agg[dst] += relu(h[src] + edge_attr)
__global__ __launch_bounds__(256)
void edge_kernel(const float* __restrict__ h,
                 const int* __restrict__ src,
                 const int* __restrict__ dst,
                 const float* __restrict__ ea,
                 float* __restrict__ agg, int E)
{
    int e = blockIdx.x * blockDim.x + threadIdx.x;
    if (e >= E) return;
    int s = __ldcs(src + e);      // streaming: evict-first
    int d = __ldcs(dst + e);
    const float2* ap = (const float2*)(ea + 6ll * e);   // 8B aligned (24B stride)
    float2 a0 = __ldcs(ap + 0);
    float2 a1 = __ldcs(ap + 1);
    float2 a2 = __ldcs(ap + 2);
    const float2* hp = (const float2*)(h + 6ll * s);    // random gather, keep in L2
    float2 h0 = __ldg(hp + 0);
    float2 h1 = __ldg(hp + 1);
    float2 h2 = __ldg(hp + 2);
    float* o = agg + 6ll * d;
    red2(o + 0, fmaxf(h0.x + a0.x, 0.f), fmaxf(h0.y + a0.y, 0.f));
    red2(o + 2, fmaxf(h1.x + a1.x, 0.f), fmaxf(h1.y + a1.y, 0.f));
    red2(o + 4, fmaxf(h2.x + a2.x, 0.f), fmaxf(h2.y + a2.y, 0.f));
}

// update: hout = [relu]((hin + agg) @ W + b); also zero agg for next layer
template<bool RELU>
__global__ __launch_bounds__(256)
void node_kernel(const float* __restrict__ hin,
                 float* __restrict__ agg,
                 const float* __restrict__ W,
                 const float* __restrict__ b,
                 float* __restrict__ hout, int N)
{
    int n = blockIdx.x * blockDim.x + threadIdx.x;
    if (n >= N) return;
    const float2* hp = (const float2*)(hin + 6ll * n);
    float2* gp = (float2*)(agg + 6ll * n);
    float2 p0 = hp[0], p1 = hp[1], p2 = hp[2];
    float2 q0 = gp[0], q1 = gp[1], q2 = gp[2];
    float t[6];
    t[0] = p0.x + q0.x; t[1] = p0.y + q0.y;
    t[2] = p1.x + q1.x; t[3] = p1.y + q1.y;
    t[4] = p2.x + q2.x; t[5] = p2.y + q2.y;
    float2 z = make_float2(0.f, 0.f);
    gp[0] = z; gp[1] = z; gp[2] = z;

    float o[6];
    #pragma unroll
    for (int j = 0; j < 6; j++) {
        float acc = __ldg(b + j);
        #pragma unroll
        for (int i = 0; i < 6; i++) acc += t[i] * __ldg(W + i * 6 + j);
        o[j] = RELU ? fmaxf(acc, 0.f) : acc;
    }
    float2* op = (float2*)(hout + 6ll * n);
    op[0] = make_float2(o[0], o[1]);
    op[1] = make_float2(o[2], o[3]);
    op[2] = make_float2(o[4], o[5]);
}

// layer-3 update fused with mean-pool accumulation (batch is sorted).
// Warp-segmented sum -> one atomic per (graph, dim) per warp.
__global__ __launch_bounds__(256)
void node3_pool_kernel(const float* __restrict__ hin,
                       const float* __restrict__ agg,
                       const float* __restrict__ W,
                       const float* __restrict__ b,
                       const int* __restrict__ batch, int N)
{
    int n = blockIdx.x * blockDim.x + threadIdx.x;
    bool valid = (n < N);
    int nn = valid ? n : (N - 1);

    const float2* hp = (const float2*)(hin + 6ll * nn);
    const float2* gp = (const float2*)(agg + 6ll * nn);
    float2 p0 = hp[0], p1 = hp[1], p2 = hp[2];
    float2 q0 = gp[0], q1 = gp[1], q2 = gp[2];
    float t[6];
    t[0] = p0.x + q0.x; t[1] = p0.y + q0.y;
    t[2] = p1.x + q1.x; t[3] = p1.y + q1.y;
    t[4] = p2.x + q2.x; t[5] = p2.y + q2.y;

    float o[6];
    #pragma unroll
    for (int j = 0; j < 6; j++) {
        float acc = __ldg(b + j);
        #pragma unroll
        for (int i = 0; i < 6; i++) acc += t[i] * __ldg(W + i * 6 + j);
        o[j] = valid ? acc : 0.f;   // invalid lanes contribute zero
    }
    float c = valid ? 1.f : 0.f;
    int g = __ldg(batch + nn);

    unsigned lane = threadIdx.x & 31u;
    unsigned peers = __match_any_sync(0xffffffffu, g);  // contiguous (sorted)
    int leader = __ffs(peers) - 1;

    #pragma unroll
    for (int j = 0; j < 6; j++) {
        float v = o[j];
        #pragma unroll
        for (int off = 1; off < 32; off <<= 1) {
            float tv = __shfl_down_sync(0xffffffffu, v, off);
            if (lane + off < 32 && ((peers >> (lane + off)) & 1u)) v += tv;
        }
        if ((int)lane == leader) atomicAdd(&g_pool[g * 6 + j], v);
    }
    {
        float v = c;
        #pragma unroll
        for (int off = 1; off < 32; off <<= 1) {
            float tv = __shfl_down_sync(0xffffffffu, v, off);
            if (lane + off < 32 && ((peers >> (lane + off)) & 1u)) v += tv;
        }
        if ((int)lane == leader) atomicAdd(&g_cnt[g], v);
    }
}

__global__ void final_kernel(const float* __restrict__ Wl,
                             const float* __restrict__ bl,
                             float* __restrict__ out, int G)
{
    int g = blockIdx.x * blockDim.x + threadIdx.x;
    if (g >= G) return;
    float c = fmaxf(g_cnt[g], 1.f);
    float s = 0.f;
    #pragma unroll
    for (int i = 0; i < 6; i++) s += (g_pool[g * 6 + i] / c) * __ldg(Wl + i);
    out[g] = s + __ldg(bl);
}

// ---------------- launch ----------------

extern "C" void kernel_launch(void* const* d_in, const int* in_sizes, int n_in,
                              void* d_out, int out_size)
{
    const float* x     = (const float*)d_in[0];
    const int*   ei    = (const int*)d_in[1];     // int32! (JAX demotes int64)
    const float* ea    = (const float*)d_in[2];
    const int*   batch = (const int*)d_in[3];
    const float* W1 = (const float*)d_in[4];
    const float* b1 = (const float*)d_in[5];
    const float* W2 = (const float*)d_in[6];
    const float* b2 = (const float*)d_in[7];
    const float* W3 = (const float*)d_in[8];
    const float* b3 = (const float*)d_in[9];
    const float* Wl = (const float*)d_in[10];
    const float* bl = (const float*)d_in[11];
    float* out = (float*)d_out;

    int N = in_sizes[0] / 6;
    int E = in_sizes[1] / 2;
    int G = out_size;

    const int* src = ei;
    const int* dst = ei + E;

    float* h;   cudaGetSymbolAddress((void**)&h,   g_h);
    float* agg; cudaGetSymbolAddress((void**)&agg, g_agg);

    int nb_node = (N + 255) / 256;
    int nb_edge = (E + 255) / 256;
    int nb_zero = (6 * N + 255) / 256;

    zero_kernel<<<nb_zero, 256>>>(6 * N);

    // layer 1 (h_in = x)
    edge_kernel<<<nb_edge, 256>>>(x, src, dst, ea, agg, E);
    node_kernel<true><<<nb_node, 256>>>(x, agg, W1, b1, h, N);

    // layer 2
    edge_kernel<<<nb_edge, 256>>>(h, src, dst, ea, agg, E);
    node_kernel<true><<<nb_node, 256>>>(h, agg, W2, b2, h, N);

    // layer 3 + pooling (fused)
    edge_kernel<<<nb_edge, 256>>>(h, src, dst, ea, agg, E);
    node3_pool_kernel<<<nb_node, 256>>>(h, agg, W3, b3, batch, N);

    final_kernel<<<(G + 127) / 128, 128>>>(Wl, bl, out, G);
}

// round 3
// speedup vs baseline: 1.2096x; 1.2096x over previous
#include <cuda_runtime.h>

// ---------------- scratch (static, no allocations) ----------------
#define MAXN 1000000
#define MAXG 1000
#define HS 8   // padded row stride (32B) for h and agg

__device__ float g_h[MAXN * HS];    // hidden state, padded rows
__device__ float g_agg[MAXN * HS];  // aggregation buffer, padded rows
__device__ float g_pool[MAXG * 6];
__device__ float g_cnt[MAXG];

__device__ __forceinline__ void red2(float* p, float a, float b) {
    asm volatile("red.global.add.v2.f32 [%0], {%1, %2};"
                 :: "l"(p), "f"(a), "f"(b) : "memory");
}
__device__ __forceinline__ void red4(float* p, float a, float b, float c, float d) {
    asm volatile("red.global.add.v4.f32 [%0], {%1, %2, %3, %4};"
                 :: "l"(p), "f"(a), "f"(b), "f"(c), "f"(d) : "memory");
}

// ---------------- kernels ----------------

// copy x -> padded g_h, zero g_agg / g_pool / g_cnt
__global__ __launch_bounds__(256)
void prep_kernel(const float* __restrict__ x, int N) {
    int n = blockIdx.x * blockDim.x + threadIdx.x;
    if (n < MAXG * 6) g_pool[n] = 0.f;
    if (n < MAXG) g_cnt[n] = 0.f;
    if (n >= N) return;
    const float2* xp = (const float2*)(x + 6ll * n);
    float2 x0 = __ldcs(xp), x1 = __ldcs(xp + 1), x2 = __ldcs(xp + 2);
    float4* hp = (float4*)(g_h + (long long)HS * n);
    hp[0] = make_float4(x0.x, x0.y, x1.x, x1.y);
    hp[1] = make_float4(x2.x, x2.y, 0.f, 0.f);
    float4* gp = (float4*)(g_agg + (long long)HS * n);
    float4 z = make_float4(0.f, 0.f, 0.f, 0.f);
    gp[0] = z; gp[1] = z;
}

// message + aggregate, 2 edges per thread:
// agg[dst] += relu(h[src] + edge_attr)
__global__ __launch_bounds__(256)
void edge_kernel(const float* __restrict__ h,
                 const int* __restrict__ src,
                 const int* __restrict__ dst,
                 const float* __restrict__ ea,
                 float* __restrict__ agg, int E)
{
    int t = blockIdx.x * blockDim.x + threadIdx.x;
    int e0 = 2 * t;
    if (e0 >= E) return;
    bool has2 = (e0 + 1 < E);

    int2 s2 = __ldcs((const int2*)(src + e0));   // e0 even -> 8B aligned
    int2 d2 = __ldcs((const int2*)(dst + e0));

    const float4* ap = (const float4*)(ea + 12ll * t);  // 48B pair, 16B aligned
    float4 a0 = __ldcs(ap + 0);
    float4 a1 = __ldcs(ap + 1);
    float4 a2 = has2 ? __ldcs(ap + 2) : make_float4(0.f, 0.f, 0.f, 0.f);

    // gathers (32B aligned rows -> 1 sector each)
    const float4* h0p = (const float4*)(h + (long long)HS * s2.x);
    float4 g0a = __ldg(h0p);
    float2 g0b = __ldg((const float2*)(h0p + 1));
    float4 g1a; float2 g1b;
    if (has2) {
        const float4* h1p = (const float4*)(h + (long long)HS * s2.y);
        g1a = __ldg(h1p);
        g1b = __ldg((const float2*)(h1p + 1));
    }

    // edge 0: attr = a0.x a0.y a0.z a0.w a1.x a1.y
    {
        float* o = agg + (long long)HS * d2.x;
        red4(o, fmaxf(g0a.x + a0.x, 0.f), fmaxf(g0a.y + a0.y, 0.f),
                fmaxf(g0a.z + a0.z, 0.f), fmaxf(g0a.w + a0.w, 0.f));
        red2(o + 4, fmaxf(g0b.x + a1.x, 0.f), fmaxf(g0b.y + a1.y, 0.f));
    }
    // edge 1: attr = a1.z a1.w a2.x a2.y a2.z a2.w
    if (has2) {
        float* o = agg + (long long)HS * d2.y;
        red4(o, fmaxf(g1a.x + a1.z, 0.f), fmaxf(g1a.y + a1.w, 0.f),
                fmaxf(g1a.z + a2.x, 0.f), fmaxf(g1a.w + a2.y, 0.f));
        red2(o + 4, fmaxf(g1b.x + a2.z, 0.f), fmaxf(g1b.y + a2.w, 0.f));
    }
}

// update: hout = relu((hin + agg) @ W + b); zero agg for next layer
__global__ __launch_bounds__(256)
void node_kernel(const float* __restrict__ hin,
                 float* __restrict__ agg,
                 const float* __restrict__ W,
                 const float* __restrict__ b,
                 float* __restrict__ hout, int N)
{
    int n = blockIdx.x * blockDim.x + threadIdx.x;
    if (n >= N) return;
    const float4* hp = (const float4*)(hin + (long long)HS * n);
    float4* gp = (float4*)(agg + (long long)HS * n);
    float4 p0 = hp[0], p1 = hp[1];
    float4 q0 = gp[0], q1 = gp[1];
    float t[6] = { p0.x + q0.x, p0.y + q0.y, p0.z + q0.z,
                   p0.w + q0.w, p1.x + q1.x, p1.y + q1.y };
    float4 z = make_float4(0.f, 0.f, 0.f, 0.f);
    gp[0] = z; gp[1] = z;

    float o[6];
    #pragma unroll
    for (int j = 0; j < 6; j++) {
        float acc = __ldg(b + j);
        #pragma unroll
        for (int i = 0; i < 6; i++) acc += t[i] * __ldg(W + i * 6 + j);
        o[j] = fmaxf(acc, 0.f);
    }
    float4* op = (float4*)(hout + (long long)HS * n);
    op[0] = make_float4(o[0], o[1], o[2], o[3]);
    op[1] = make_float4(o[4], o[5], 0.f, 0.f);
}

// layer-3 update fused with mean-pool accumulation (batch is sorted).
__global__ __launch_bounds__(256)
void node3_pool_kernel(const float* __restrict__ hin,
                       const float* __restrict__ agg,
                       const float* __restrict__ W,
                       const float* __restrict__ b,
                       const int* __restrict__ batch, int N)
{
    int n = blockIdx.x * blockDim.x + threadIdx.x;
    bool valid = (n < N);
    int nn = valid ? n : (N - 1);

    const float4* hp = (const float4*)(hin + (long long)HS * nn);
    const float4* gp = (const float4*)(agg + (long long)HS * nn);
    float4 p0 = hp[0], p1 = hp[1];
    float4 q0 = gp[0], q1 = gp[1];
    float t[6] = { p0.x + q0.x, p0.y + q0.y, p0.z + q0.z,
                   p0.w + q0.w, p1.x + q1.x, p1.y + q1.y };

    float o[6];
    #pragma unroll
    for (int j = 0; j < 6; j++) {
        float acc = __ldg(b + j);
        #pragma unroll
        for (int i = 0; i < 6; i++) acc += t[i] * __ldg(W + i * 6 + j);
        o[j] = valid ? acc : 0.f;
    }
    float c = valid ? 1.f : 0.f;
    int g = __ldg(batch + nn);

    unsigned lane = threadIdx.x & 31u;
    unsigned peers = __match_any_sync(0xffffffffu, g);  // contiguous (sorted)
    int leader = __ffs(peers) - 1;

    #pragma unroll
    for (int j = 0; j < 6; j++) {
        float v = o[j];
        #pragma unroll
        for (int off = 1; off < 32; off <<= 1) {
            float tv = __shfl_down_sync(0xffffffffu, v, off);
            if (lane + off < 32 && ((peers >> (lane + off)) & 1u)) v += tv;
        }
        if ((int)lane == leader) atomicAdd(&g_pool[g * 6 + j], v);
    }
    {
        float v = c;
        #pragma unroll
        for (int off = 1; off < 32; off <<= 1) {
            float tv = __shfl_down_sync(0xffffffffu, v, off);
            if (lane + off < 32 && ((peers >> (lane + off)) & 1u)) v += tv;
        }
        if ((int)lane == leader) atomicAdd(&g_cnt[g], v);
    }
}

__global__ void final_kernel(const float* __restrict__ Wl,
                             const float* __restrict__ bl,
                             float* __restrict__ out, int G)
{
    int g = blockIdx.x * blockDim.x + threadIdx.x;
    if (g >= G) return;
    float c = fmaxf(g_cnt[g], 1.f);
    float s = 0.f;
    #pragma unroll
    for (int i = 0; i < 6; i++) s += (g_pool[g * 6 + i] / c) * __ldg(Wl + i);
    out[g] = s + __ldg(bl);
}

// ---------------- launch ----------------

extern "C" void kernel_launch(void* const* d_in, const int* in_sizes, int n_in,
                              void* d_out, int out_size)
{
    const float* x     = (const float*)d_in[0];
    const int*   ei    = (const int*)d_in[1];     // int32 (JAX demotes int64)
    const float* ea    = (const float*)d_in[2];
    const int*   batch = (const int*)d_in[3];
    const float* W1 = (const float*)d_in[4];
    const float* b1 = (const float*)d_in[5];
    const float* W2 = (const float*)d_in[6];
    const float* b2 = (const float*)d_in[7];
    const float* W3 = (const float*)d_in[8];
    const float* b3 = (const float*)d_in[9];
    const float* Wl = (const float*)d_in[10];
    const float* bl = (const float*)d_in[11];
    float* out = (float*)d_out;

    int N = in_sizes[0] / 6;
    int E = in_sizes[1] / 2;
    int G = out_size;

    const int* src = ei;
    const int* dst = ei + E;

    float* h;   cudaGetSymbolAddress((void**)&h,   g_h);
    float* agg; cudaGetSymbolAddress((void**)&agg, g_agg);

    int nb_node = (N + 255) / 256;
    int nb_edge = ((E + 1) / 2 + 255) / 256;

    prep_kernel<<<nb_node, 256>>>(x, N);

    // layer 1 (h_in = padded x, already in g_h)
    edge_kernel<<<nb_edge, 256>>>(h, src, dst, ea, agg, E);
    node_kernel<<<nb_node, 256>>>(h, agg, W1, b1, h, N);

    // layer 2
    edge_kernel<<<nb_edge, 256>>>(h, src, dst, ea, agg, E);
    node_kernel<<<nb_node, 256>>>(h, agg, W2, b2, h, N);

    // layer 3 + pooling (fused)
    edge_kernel<<<nb_edge, 256>>>(h, src, dst, ea, agg, E);
    node3_pool_kernel<<<nb_node, 256>>>(h, agg, W3, b3, batch, N);

    final_kernel<<<(G + 127) / 128, 128>>>(Wl, bl, out, G);
}

// round 4
// speedup vs baseline: 1.8473x; 1.5272x over previous
#include <cuda_runtime.h>
#include <cuda_fp16.h>

// ---------------- scratch (static, no allocations) ----------------
#define MAXN 1000000
#define MAXG 1000
#define HS 8   // halves per row (16B) for h and agg

__device__ __half g_h[MAXN * HS];    // hidden state, fp16 padded rows (16B)
__device__ __half g_agg[MAXN * HS];  // aggregation buffer, fp16 (16B rows)
__device__ float  g_pool[MAXG * 6];
__device__ float  g_cnt[MAXG];

// one 16B fp16 vector reduction: 8 halves (sm_90+)
__device__ __forceinline__ void red8h(__half* p, unsigned r0, unsigned r1,
                                      unsigned r2, unsigned r3) {
    asm volatile("red.global.add.noftz.v4.f16x2 [%0], {%1, %2, %3, %4};"
                 :: "l"(p), "r"(r0), "r"(r1), "r"(r2), "r"(r3) : "memory");
}

__device__ __forceinline__ unsigned pack2(float a, float b) {
    __half2 h = __floats2half2_rn(a, b);
    return *reinterpret_cast<unsigned*>(&h);
}

// ---------------- kernels ----------------

// copy x -> fp16 g_h, zero g_agg / g_pool / g_cnt
__global__ __launch_bounds__(256)
void prep_kernel(const float* __restrict__ x, int N) {
    int n = blockIdx.x * blockDim.x + threadIdx.x;
    if (n < MAXG * 6) g_pool[n] = 0.f;
    if (n < MAXG) g_cnt[n] = 0.f;
    if (n >= N) return;
    const float2* xp = (const float2*)(x + 6ll * n);
    float2 x0 = __ldcs(xp), x1 = __ldcs(xp + 1), x2 = __ldcs(xp + 2);
    uint4 hv;
    hv.x = pack2(x0.x, x0.y);
    hv.y = pack2(x1.x, x1.y);
    hv.z = pack2(x2.x, x2.y);
    hv.w = 0u;
    *(uint4*)(g_h + (long long)HS * n) = hv;
    *(uint4*)(g_agg + (long long)HS * n) = make_uint4(0u, 0u, 0u, 0u);
}

// message + aggregate, 2 edges per thread:
// agg[dst] += relu(h[src] + edge_attr)   (single v4.f16x2 red per edge)
__global__ __launch_bounds__(256)
void edge_kernel(const __half* __restrict__ h,
                 const int* __restrict__ src,
                 const int* __restrict__ dst,
                 const float* __restrict__ ea,
                 __half* __restrict__ agg, int E)
{
    int t = blockIdx.x * blockDim.x + threadIdx.x;
    int e0 = 2 * t;
    if (e0 >= E) return;
    bool has2 = (e0 + 1 < E);

    int2 s2 = __ldcs((const int2*)(src + e0));
    int2 d2 = __ldcs((const int2*)(dst + e0));

    const float4* ap = (const float4*)(ea + 12ll * t);  // 48B for 2 edges
    float4 a0 = __ldcs(ap + 0);
    float4 a1 = __ldcs(ap + 1);
    float4 a2 = has2 ? __ldcs(ap + 2) : make_float4(0.f, 0.f, 0.f, 0.f);

    // gathers: one 16B load per edge
    uint4 hv0 = __ldg((const uint4*)(h + (long long)HS * s2.x));
    uint4 hv1 = has2 ? __ldg((const uint4*)(h + (long long)HS * s2.y))
                     : make_uint4(0u, 0u, 0u, 0u);

    // edge 0: attr = a0.x a0.y a0.z a0.w a1.x a1.y
    {
        float2 f0 = __half22float2(*reinterpret_cast<__half2*>(&hv0.x));
        float2 f1 = __half22float2(*reinterpret_cast<__half2*>(&hv0.y));
        float2 f2 = __half22float2(*reinterpret_cast<__half2*>(&hv0.z));
        unsigned m0 = pack2(fmaxf(f0.x + a0.x, 0.f), fmaxf(f0.y + a0.y, 0.f));
        unsigned m1 = pack2(fmaxf(f1.x + a0.z, 0.f), fmaxf(f1.y + a0.w, 0.f));
        unsigned m2 = pack2(fmaxf(f2.x + a1.x, 0.f), fmaxf(f2.y + a1.y, 0.f));
        red8h(agg + (long long)HS * d2.x, m0, m1, m2, 0u);
    }
    // edge 1: attr = a1.z a1.w a2.x a2.y a2.z a2.w
    if (has2) {
        float2 f0 = __half22float2(*reinterpret_cast<__half2*>(&hv1.x));
        float2 f1 = __half22float2(*reinterpret_cast<__half2*>(&hv1.y));
        float2 f2 = __half22float2(*reinterpret_cast<__half2*>(&hv1.z));
        unsigned m0 = pack2(fmaxf(f0.x + a1.z, 0.f), fmaxf(f0.y + a1.w, 0.f));
        unsigned m1 = pack2(fmaxf(f1.x + a2.x, 0.f), fmaxf(f1.y + a2.y, 0.f));
        unsigned m2 = pack2(fmaxf(f2.x + a2.z, 0.f), fmaxf(f2.y + a2.w, 0.f));
        red8h(agg + (long long)HS * d2.y, m0, m1, m2, 0u);
    }
}

// update: hout = relu((hin + agg) @ W + b); zero agg for next layer
__global__ __launch_bounds__(256)
void node_kernel(const __half* __restrict__ hin,
                 __half* __restrict__ agg,
                 const float* __restrict__ W,
                 const float* __restrict__ b,
                 __half* __restrict__ hout, int N)
{
    int n = blockIdx.x * blockDim.x + threadIdx.x;
    if (n >= N) return;
    uint4 hv = *(const uint4*)(hin + (long long)HS * n);
    uint4* gp = (uint4*)(agg + (long long)HS * n);
    uint4 gv = *gp;
    *gp = make_uint4(0u, 0u, 0u, 0u);

    float2 h0 = __half22float2(*reinterpret_cast<__half2*>(&hv.x));
    float2 h1 = __half22float2(*reinterpret_cast<__half2*>(&hv.y));
    float2 h2 = __half22float2(*reinterpret_cast<__half2*>(&hv.z));
    float2 q0 = __half22float2(*reinterpret_cast<__half2*>(&gv.x));
    float2 q1 = __half22float2(*reinterpret_cast<__half2*>(&gv.y));
    float2 q2 = __half22float2(*reinterpret_cast<__half2*>(&gv.z));
    float t[6] = { h0.x + q0.x, h0.y + q0.y, h1.x + q1.x,
                   h1.y + q1.y, h2.x + q2.x, h2.y + q2.y };

    float o[6];
    #pragma unroll
    for (int j = 0; j < 6; j++) {
        float acc = __ldg(b + j);
        #pragma unroll
        for (int i = 0; i < 6; i++) acc += t[i] * __ldg(W + i * 6 + j);
        o[j] = fmaxf(acc, 0.f);
    }
    uint4 ov;
    ov.x = pack2(o[0], o[1]);
    ov.y = pack2(o[2], o[3]);
    ov.z = pack2(o[4], o[5]);
    ov.w = 0u;
    *(uint4*)(hout + (long long)HS * n) = ov;
}

// layer-3 update fused with mean-pool accumulation (batch is sorted).
__global__ __launch_bounds__(256)
void node3_pool_kernel(const __half* __restrict__ hin,
                       const __half* __restrict__ agg,
                       const float* __restrict__ W,
                       const float* __restrict__ b,
                       const int* __restrict__ batch, int N)
{
    int n = blockIdx.x * blockDim.x + threadIdx.x;
    bool valid = (n < N);
    int nn = valid ? n : (N - 1);

    uint4 hv = *(const uint4*)(hin + (long long)HS * nn);
    uint4 gv = *(const uint4*)(agg + (long long)HS * nn);

    float2 h0 = __half22float2(*reinterpret_cast<__half2*>(&hv.x));
    float2 h1 = __half22float2(*reinterpret_cast<__half2*>(&hv.y));
    float2 h2 = __half22float2(*reinterpret_cast<__half2*>(&hv.z));
    float2 q0 = __half22float2(*reinterpret_cast<__half2*>(&gv.x));
    float2 q1 = __half22float2(*reinterpret_cast<__half2*>(&gv.y));
    float2 q2 = __half22float2(*reinterpret_cast<__half2*>(&gv.z));
    float t[6] = { h0.x + q0.x, h0.y + q0.y, h1.x + q1.x,
                   h1.y + q1.y, h2.x + q2.x, h2.y + q2.y };

    float o[6];
    #pragma unroll
    for (int j = 0; j < 6; j++) {
        float acc = __ldg(b + j);
        #pragma unroll
        for (int i = 0; i < 6; i++) acc += t[i] * __ldg(W + i * 6 + j);
        o[j] = valid ? acc : 0.f;
    }
    float c = valid ? 1.f : 0.f;
    int g = __ldg(batch + nn);

    unsigned lane = threadIdx.x & 31u;
    unsigned peers = __match_any_sync(0xffffffffu, g);  // contiguous (sorted)
    int leader = __ffs(peers) - 1;

    #pragma unroll
    for (int j = 0; j < 6; j++) {
        float v = o[j];
        #pragma unroll
        for (int off = 1; off < 32; off <<= 1) {
            float tv = __shfl_down_sync(0xffffffffu, v, off);
            if (lane + off < 32 && ((peers >> (lane + off)) & 1u)) v += tv;
        }
        if ((int)lane == leader) atomicAdd(&g_pool[g * 6 + j], v);
    }
    {
        float v = c;
        #pragma unroll
        for (int off = 1; off < 32; off <<= 1) {
            float tv = __shfl_down_sync(0xffffffffu, v, off);
            if (lane + off < 32 && ((peers >> (lane + off)) & 1u)) v += tv;
        }
        if ((int)lane == leader) atomicAdd(&g_cnt[g], v);
    }
}

__global__ void final_kernel(const float* __restrict__ Wl,
                             const float* __restrict__ bl,
                             float* __restrict__ out, int G)
{
    int g = blockIdx.x * blockDim.x + threadIdx.x;
    if (g >= G) return;
    float c = fmaxf(g_cnt[g], 1.f);
    float s = 0.f;
    #pragma unroll
    for (int i = 0; i < 6; i++) s += (g_pool[g * 6 + i] / c) * __ldg(Wl + i);
    out[g] = s + __ldg(bl);
}

// ---------------- launch ----------------

extern "C" void kernel_launch(void* const* d_in, const int* in_sizes, int n_in,
                              void* d_out, int out_size)
{
    const float* x     = (const float*)d_in[0];
    const int*   ei    = (const int*)d_in[1];     // int32 (JAX demotes int64)
    const float* ea    = (const float*)d_in[2];
    const int*   batch = (const int*)d_in[3];
    const float* W1 = (const float*)d_in[4];
    const float* b1 = (const float*)d_in[5];
    const float* W2 = (const float*)d_in[6];
    const float* b2 = (const float*)d_in[7];
    const float* W3 = (const float*)d_in[8];
    const float* b3 = (const float*)d_in[9];
    const float* Wl = (const float*)d_in[10];
    const float* bl = (const float*)d_in[11];
    float* out = (float*)d_out;

    int N = in_sizes[0] / 6;
    int E = in_sizes[1] / 2;
    int G = out_size;

    const int* src = ei;
    const int* dst = ei + E;

    __half* h;   cudaGetSymbolAddress((void**)&h,   g_h);
    __half* agg; cudaGetSymbolAddress((void**)&agg, g_agg);

    int nb_node = (N + 255) / 256;
    int nb_edge = ((E + 1) / 2 + 255) / 256;

    prep_kernel<<<nb_node, 256>>>(x, N);

    // layer 1 (h_in = fp16 x, already in g_h)
    edge_kernel<<<nb_edge, 256>>>(h, src, dst, ea, agg, E);
    node_kernel<<<nb_node, 256>>>(h, agg, W1, b1, h, N);

    // layer 2
    edge_kernel<<<nb_edge, 256>>>(h, src, dst, ea, agg, E);
    node_kernel<<<nb_node, 256>>>(h, agg, W2, b2, h, N);

    // layer 3 + pooling (fused)
    edge_kernel<<<nb_edge, 256>>>(h, src, dst, ea, agg, E);
    node3_pool_kernel<<<nb_node, 256>>>(h, agg, W3, b3, batch, N);

    final_kernel<<<(G + 127) / 128, 128>>>(Wl, bl, out, G);
}